// round 10
// baseline (speedup 1.0000x reference)
#include <cuda_runtime.h>
#include <cuda_bf16.h>
#include <math.h>

// Problem constants
#define BB 1024
#define SS 512
#define DD 768
#define H1 256
#define H2 64
#define NC 4
#define FEAT (3 * DD)    // 2304
#define KS 8             // K-split for layer 1
#define KCH (FEAT / KS)  // 288
#define MB 16            // batches per layer-1 block

typedef unsigned long long u64;

// Packed f32x2 helpers (Blackwell): one FFMA2 = 2 fp32 FMAs, PTX-only.
#define PACKF2(d, a, b) \
    asm("mov.b64 %0, {%1, %2};" : "=l"(d) : "f"(a), "f"(b))
#define UNPACKF2(lo, hi, v) \
    asm("mov.b64 {%0, %1}, %2;" : "=f"(lo), "=f"(hi) : "l"(v))
#define FMAF2(d, a, b, c) \
    asm("fma.rn.f32x2 %0, %1, %2, %3;" : "=l"(d) : "l"(a), "l"(b), "l"(c))

// Scratch
__device__ float g_feat[(size_t)BB * FEAT];     // 9.4 MB
__device__ float g_part[(size_t)KS * BB * H1];  // 8 MB

// ---------------------------------------------------------------------------
// Kernel 1: span means + cls -> g_feat, reading the span UNION once when the
// spans overlap. grid (B, 2) x block (96, 4): 96 float4 cols x 4 row-strides.
// Overlap case: 3 contiguous segments with block-uniform ownership.
// ---------------------------------------------------------------------------
__global__ void __launch_bounds__(384) span_feat_kernel(
    const float* __restrict__ x,
    const int* __restrict__ e1_span,
    const int* __restrict__ e2_span)
{
    __shared__ float4 s1p[4][96];
    __shared__ float4 s2p[4][96];

    const int b   = blockIdx.x;
    const int col = threadIdx.x + blockIdx.y * 96;  // float4 col 0..191
    const int ty  = threadIdx.y;                    // 0..3

    const float4* xb = reinterpret_cast<const float4*>(x + (size_t)b * SS * DD);

    const int lo1 = e1_span[2 * b];
    const int hi1 = max(e1_span[2 * b + 1], lo1 + 1);
    const int lo2 = e2_span[2 * b];
    const int hi2 = max(e2_span[2 * b + 1], lo2 + 1);

    const int olo = max(lo1, lo2);
    const int ohi = min(hi1, hi2);

    float4 s1 = make_float4(0.f, 0.f, 0.f, 0.f);
    float4 s2 = make_float4(0.f, 0.f, 0.f, 0.f);

    if (olo < ohi) {
        const int mlo = min(lo1, lo2);
        const int mhi = max(hi1, hi2);

        float4 sA = make_float4(0.f, 0.f, 0.f, 0.f);
        float4 sB = make_float4(0.f, 0.f, 0.f, 0.f);
        float4 sC = make_float4(0.f, 0.f, 0.f, 0.f);

        #pragma unroll 4
        for (int r = mlo + ty; r < olo; r += 4) {
            float4 v = xb[(size_t)r * (DD / 4) + col];
            sA.x += v.x; sA.y += v.y; sA.z += v.z; sA.w += v.w;
        }
        #pragma unroll 4
        for (int r = olo + ty; r < ohi; r += 4) {
            float4 v = xb[(size_t)r * (DD / 4) + col];
            sB.x += v.x; sB.y += v.y; sB.z += v.z; sB.w += v.w;
        }
        #pragma unroll 4
        for (int r = ohi + ty; r < mhi; r += 4) {
            float4 v = xb[(size_t)r * (DD / 4) + col];
            sC.x += v.x; sC.y += v.y; sC.z += v.z; sC.w += v.w;
        }

        const float a1 = (lo1 < lo2) ? 1.f : 0.f;
        const float a2 = (lo2 < lo1) ? 1.f : 0.f;
        const float c1 = (hi1 > hi2) ? 1.f : 0.f;
        const float c2 = (hi2 > hi1) ? 1.f : 0.f;

        s1.x = sB.x + a1 * sA.x + c1 * sC.x;
        s1.y = sB.y + a1 * sA.y + c1 * sC.y;
        s1.z = sB.z + a1 * sA.z + c1 * sC.z;
        s1.w = sB.w + a1 * sA.w + c1 * sC.w;
        s2.x = sB.x + a2 * sA.x + c2 * sC.x;
        s2.y = sB.y + a2 * sA.y + c2 * sC.y;
        s2.z = sB.z + a2 * sA.z + c2 * sC.z;
        s2.w = sB.w + a2 * sA.w + c2 * sC.w;
    } else {
        #pragma unroll 4
        for (int r = lo1 + ty; r < hi1; r += 4) {
            float4 v = xb[(size_t)r * (DD / 4) + col];
            s1.x += v.x; s1.y += v.y; s1.z += v.z; s1.w += v.w;
        }
        #pragma unroll 4
        for (int r = lo2 + ty; r < hi2; r += 4) {
            float4 v = xb[(size_t)r * (DD / 4) + col];
            s2.x += v.x; s2.y += v.y; s2.z += v.z; s2.w += v.w;
        }
    }

    s1p[ty][threadIdx.x] = s1;
    s2p[ty][threadIdx.x] = s2;
    __syncthreads();

    float4* fb = reinterpret_cast<float4*>(g_feat + (size_t)b * FEAT);

    if (ty == 0) {
        const float inv1 = 1.0f / (float)(hi1 - lo1);
        float4 a = s1p[0][threadIdx.x], bq = s1p[1][threadIdx.x];
        float4 c = s1p[2][threadIdx.x], d  = s1p[3][threadIdx.x];
        fb[col] = make_float4((a.x + bq.x + c.x + d.x) * inv1,
                              (a.y + bq.y + c.y + d.y) * inv1,
                              (a.z + bq.z + c.z + d.z) * inv1,
                              (a.w + bq.w + c.w + d.w) * inv1);
    } else if (ty == 1) {
        const float inv2 = 1.0f / (float)(hi2 - lo2);
        float4 a = s2p[0][threadIdx.x], bq = s2p[1][threadIdx.x];
        float4 c = s2p[2][threadIdx.x], d  = s2p[3][threadIdx.x];
        fb[DD / 4 + col] = make_float4((a.x + bq.x + c.x + d.x) * inv2,
                                       (a.y + bq.y + c.y + d.y) * inv2,
                                       (a.z + bq.z + c.z + d.z) * inv2,
                                       (a.w + bq.w + c.w + d.w) * inv2);
    } else if (ty == 2) {
        fb[DD / 2 + col] = xb[col];   // cls = row 0
    }
}

// ---------------------------------------------------------------------------
// Kernel 2a: layer-1 partial GEMM, K-split, register-tiled 4n x 4mb,
// inner product via packed fma.rn.f32x2 (2 fp32 FMAs per instruction).
// grid (B/MB, KS) = (64, 8), block 256.
// ---------------------------------------------------------------------------
__global__ void __launch_bounds__(256) l1_partial_kernel(
    const float* __restrict__ W1)
{
    __shared__ float sfeat[MB][KCH];   // 18 KB

    const int t   = threadIdx.x;
    const int bg  = blockIdx.x;        // 0..63
    const int ks  = blockIdx.y;        // 0..7
    const int n0  = (t & 63) * 4;
    const int mb0 = (t >> 6) * 4;

    // Stage feat chunk: MB rows x KCH cols = 1152 float4
    {
        const float* gf = g_feat + (size_t)(bg * MB) * FEAT + ks * KCH;
        for (int idx = t; idx < MB * (KCH / 4); idx += 256) {
            const int mb = idx / (KCH / 4);
            const int i  = idx - mb * (KCH / 4);
            reinterpret_cast<float4*>(&sfeat[mb][0])[i] =
                reinterpret_cast<const float4*>(gf + (size_t)mb * FEAT)[i];
        }
    }
    __syncthreads();

    // acc[mb][0] = packed (n0+0, n0+1); acc[mb][1] = packed (n0+2, n0+3)
    u64 acc[4][2];
    #pragma unroll
    for (int i = 0; i < 4; ++i) { acc[i][0] = 0ull; acc[i][1] = 0ull; }

    const float4* w = reinterpret_cast<const float4*>(
        W1 + (size_t)(ks * KCH) * H1 + n0);

    #pragma unroll 4
    for (int k = 0; k < KCH; ++k) {
        const float4 wv = __ldg(&w[(size_t)k * (H1 / 4)]);
        u64 wlo, whi;
        PACKF2(wlo, wv.x, wv.y);
        PACKF2(whi, wv.z, wv.w);
        #pragma unroll
        for (int mb = 0; mb < 4; ++mb) {
            const float f = sfeat[mb0 + mb][k];
            u64 ff;
            PACKF2(ff, f, f);
            FMAF2(acc[mb][0], wlo, ff, acc[mb][0]);
            FMAF2(acc[mb][1], whi, ff, acc[mb][1]);
        }
    }

    // g_part[ks][bg*MB + mb][n]
    float* gp = g_part + ((size_t)ks * BB + bg * MB + mb0) * H1 + n0;
    #pragma unroll
    for (int mb = 0; mb < 4; ++mb) {
        float4 o;
        UNPACKF2(o.x, o.y, acc[mb][0]);
        UNPACKF2(o.z, o.w, acc[mb][1]);
        *reinterpret_cast<float4*>(gp + (size_t)mb * H1) = o;
    }
}

// ---------------------------------------------------------------------------
// Kernel 2b: finish. One block per batch (1024 blocks, 256 threads).
// ---------------------------------------------------------------------------
__global__ void __launch_bounds__(256) mlp_finish_kernel(
    const float* __restrict__ b1,
    const float* __restrict__ W2, const float* __restrict__ b2,
    const float* __restrict__ W3, const float* __restrict__ b3,
    float* __restrict__ out)
{
    __shared__ float sh1[H1];
    __shared__ float spart[4][H2];
    __shared__ float sh2[H2];
    __shared__ float slog[NC];

    const int t = threadIdx.x;
    const int b = blockIdx.x;

    // h1 = relu(b1 + sum_ks part)
    {
        const float* gp = g_part + (size_t)b * H1 + t;
        float a = b1[t];
        #pragma unroll
        for (int ks = 0; ks < KS; ++ks)
            a += gp[(size_t)ks * BB * H1];
        sh1[t] = fmaxf(a, 0.f);
    }
    __syncthreads();

    // Layer 2: 256 threads = 64 n x 4 k-quarters
    {
        const int n = t & 63;
        const int q = t >> 6;
        float a = 0.f;
        #pragma unroll 8
        for (int k = q * 64; k < (q + 1) * 64; ++k)
            a = fmaf(sh1[k], W2[k * H2 + n], a);
        spart[q][n] = a;
    }
    __syncthreads();
    if (t < H2) {
        float a = b2[t] + spart[0][t] + spart[1][t] + spart[2][t] + spart[3][t];
        sh2[t] = fmaxf(a, 0.f);
    }
    __syncthreads();

    // Layer 3: 4 warps, warp n computes logit n via shuffle reduce
    if (t < 128) {
        const int n    = t >> 5;
        const int lane = t & 31;
        float a = sh2[lane] * W3[lane * NC + n]
                + sh2[lane + 32] * W3[(lane + 32) * NC + n];
        #pragma unroll
        for (int off = 16; off > 0; off >>= 1)
            a += __shfl_down_sync(0xFFFFFFFF, a, off);
        if (lane == 0) slog[n] = a + b3[n];
    }
    __syncthreads();

    if (t == 0) {
        float l0 = slog[0], l1 = slog[1], l2 = slog[2], l3 = slog[3];
        float m = fmaxf(fmaxf(l0, l1), fmaxf(l2, l3));
        float e0 = __expf(l0 - m), e1 = __expf(l1 - m);
        float e2 = __expf(l2 - m), e3 = __expf(l3 - m);
        float inv = 1.0f / (e0 + e1 + e2 + e3);
        float* o = out + (size_t)b * NC;
        o[0] = e0 * inv; o[1] = e1 * inv; o[2] = e2 * inv; o[3] = e3 * inv;
    }
}

// ---------------------------------------------------------------------------
// Launch
// Inputs: x, e1_span, e2_span, W1, b1, W2, b2, W3, b3
// ---------------------------------------------------------------------------
extern "C" void kernel_launch(void* const* d_in, const int* in_sizes, int n_in,
                              void* d_out, int out_size)
{
    const float* x  = (const float*)d_in[0];
    const int* e1   = (const int*)d_in[1];
    const int* e2   = (const int*)d_in[2];
    const float* W1 = (const float*)d_in[3];
    const float* b1 = (const float*)d_in[4];
    const float* W2 = (const float*)d_in[5];
    const float* b2 = (const float*)d_in[6];
    const float* W3 = (const float*)d_in[7];
    const float* b3 = (const float*)d_in[8];
    float* out      = (float*)d_out;

    dim3 g1(BB, 2);
    dim3 t1(96, 4);
    span_feat_kernel<<<g1, t1>>>(x, e1, e2);

    dim3 g2(BB / MB, KS);
    l1_partial_kernel<<<g2, 256>>>(W1);

    mlp_finish_kernel<<<BB, 256>>>(b1, W2, b2, W3, b3, out);
}